// round 1
// baseline (speedup 1.0000x reference)
#include <cuda_runtime.h>
#include <math.h>

#define T_TOK 512
#define DDIM  1024
#define FDIM  4096
#define NEXP  8
#define RNK   16
#define TOPK  2
#define LSCALE 2.0f
#define EPS   1e-6f

// ---------------- scratch (device globals; no allocation allowed) ----------
__device__ float g_t[T_TOK * DDIM];                 // normalized tokens
__device__ float g_base1[T_TOK * FDIM];             // t @ w1^T
__device__ float g_base3[T_TOK * FDIM];             // t @ w3^T
__device__ int   g_idx[T_TOK * TOPK];               // routed expert ids
__device__ float g_wgt[T_TOK * TOPK];               // renormalized weights
__device__ float g_lr1[T_TOK * TOPK * RNK];         // SCALING * t@a1[e]^T
__device__ float g_lr3[T_TOK * TOPK * RNK];
__device__ float g_act[T_TOK * TOPK * FDIM];        // silu(h1)*h3 per (t,slot)
__device__ float g_lr2[T_TOK * TOPK * RNK];         // SCALING * act@a2[e]^T
__device__ float g_y[T_TOK * TOPK * DDIM];          // act @ w2^T

// ---------------- K1: RMSNorm ----------------------------------------------
__global__ void k_rmsnorm(const float* __restrict__ x, const float* __restrict__ nw) {
    int t = blockIdx.x;
    const float* xr = x + t * DDIM;
    float ss = 0.f;
    for (int i = threadIdx.x; i < DDIM; i += blockDim.x) {
        float v = xr[i];
        ss += v * v;
    }
    __shared__ float sred[32];
    for (int o = 16; o; o >>= 1) ss += __shfl_xor_sync(0xffffffffu, ss, o);
    if ((threadIdx.x & 31) == 0) sred[threadIdx.x >> 5] = ss;
    __syncthreads();
    if (threadIdx.x < 32) {
        float v = (threadIdx.x < (blockDim.x >> 5)) ? sred[threadIdx.x] : 0.f;
        for (int o = 16; o; o >>= 1) v += __shfl_xor_sync(0xffffffffu, v, o);
        if (threadIdx.x == 0) sred[0] = v;
    }
    __syncthreads();
    float scale = rsqrtf(sred[0] / (float)DDIM + EPS);
    for (int i = threadIdx.x; i < DDIM; i += blockDim.x)
        g_t[t * DDIM + i] = xr[i] * scale * nw[i];
}

// ---------------- K2: router (softmax -> top2 -> renorm) --------------------
__global__ void k_router(const float* __restrict__ gw) {
    int t = blockIdx.x;
    int w = threadIdx.x >> 5, l = threadIdx.x & 31;   // 8 warps, warp = expert
    const float* tr = g_t + t * DDIM;
    const float* gr = gw + w * DDIM;
    float s = 0.f;
    for (int i = l; i < DDIM; i += 32) s += tr[i] * gr[i];
    for (int o = 16; o; o >>= 1) s += __shfl_xor_sync(0xffffffffu, s, o);
    __shared__ float logits[NEXP];
    if (l == 0) logits[w] = s;
    __syncthreads();
    if (threadIdx.x == 0) {
        float mx = logits[0];
        for (int e = 1; e < NEXP; e++) mx = fmaxf(mx, logits[e]);
        float p[NEXP], sum = 0.f;
        for (int e = 0; e < NEXP; e++) { p[e] = expf(logits[e] - mx); sum += p[e]; }
        for (int e = 0; e < NEXP; e++) p[e] /= sum;
        int i0 = 0;
        for (int e = 1; e < NEXP; e++) if (p[e] > p[i0]) i0 = e;
        int i1 = -1;
        for (int e = 0; e < NEXP; e++) {
            if (e == i0) continue;
            if (i1 < 0 || p[e] > p[i1]) i1 = e;
        }
        float w0 = p[i0], w1 = p[i1], tw = w0 + w1;
        g_idx[t * 2 + 0] = i0;  g_idx[t * 2 + 1] = i1;
        g_wgt[t * 2 + 0] = w0 / tw;  g_wgt[t * 2 + 1] = w1 / tw;
    }
}

// ---------------- K3: LoRA-A up projections (rank-16 dots) ------------------
__global__ void k_lora_a(const float* __restrict__ a1, const float* __restrict__ a3) {
    int t = blockIdx.x, k = blockIdx.y;
    int row = t * TOPK + k;
    int e = g_idx[row];
    const float* tr = g_t + t * DDIM;
    int w = threadIdx.x >> 5, l = threadIdx.x & 31;  // 8 warps
    for (int task = w; task < 2 * RNK; task += 8) {
        int mat = task >> 4, r = task & 15;
        const float* ar = (mat ? a3 : a1) + ((size_t)e * RNK + r) * DDIM;
        float s = 0.f;
        for (int i = l; i < DDIM; i += 32) s += tr[i] * ar[i];
        for (int o = 16; o; o >>= 1) s += __shfl_xor_sync(0xffffffffu, s, o);
        if (l == 0) {
            float* dst = mat ? g_lr3 : g_lr1;
            dst[row * RNK + r] = LSCALE * s;
        }
    }
}

// ---------------- tiled NT SGEMM: C[M,N] = A[M,K] @ B[N,K]^T ----------------
// BM=BN=64, BK=16, 256 threads, 4x4 accum per thread. All dims divisible.
#define BM 64
#define BN 64
#define BK 16
__global__ void __launch_bounds__(256)
k_sgemm_nt(int M, int N, int K,
           const float* __restrict__ A, const float* __restrict__ B,
           float* __restrict__ C) {
    __shared__ float As[BK][BM];
    __shared__ float Bs[BK][BN];
    int bm = blockIdx.y * BM, bn = blockIdx.x * BN;
    int tid = threadIdx.x;
    int tx = tid & 15;        // output col group
    int ty = tid >> 4;        // output row group
    int lr = tid >> 2;        // 0..63 load row
    int lc = (tid & 3) * 4;   // 0,4,8,12 load k offset
    float acc[4][4] = {};

    const float* Ap = A + (size_t)(bm + lr) * K + lc;
    const float* Bp = B + (size_t)(bn + lr) * K + lc;

    for (int k0 = 0; k0 < K; k0 += BK) {
        float4 av = *(const float4*)(Ap + k0);
        As[lc + 0][lr] = av.x; As[lc + 1][lr] = av.y;
        As[lc + 2][lr] = av.z; As[lc + 3][lr] = av.w;
        float4 bv = *(const float4*)(Bp + k0);
        Bs[lc + 0][lr] = bv.x; Bs[lc + 1][lr] = bv.y;
        Bs[lc + 2][lr] = bv.z; Bs[lc + 3][lr] = bv.w;
        __syncthreads();
#pragma unroll
        for (int kk = 0; kk < BK; kk++) {
            float4 a = *(const float4*)&As[kk][ty * 4];
            float4 b = *(const float4*)&Bs[kk][tx * 4];
            float ar[4] = {a.x, a.y, a.z, a.w};
            float br[4] = {b.x, b.y, b.z, b.w};
#pragma unroll
            for (int i = 0; i < 4; i++)
#pragma unroll
                for (int j = 0; j < 4; j++)
                    acc[i][j] = fmaf(ar[i], br[j], acc[i][j]);
        }
        __syncthreads();
    }
#pragma unroll
    for (int i = 0; i < 4; i++) {
        float4 v = make_float4(acc[i][0], acc[i][1], acc[i][2], acc[i][3]);
        *(float4*)(C + (size_t)(bm + ty * 4 + i) * N + bn + tx * 4) = v;
    }
}

// ---------------- K5: fused LoRA-B + SwiGLU ---------------------------------
__global__ void k_act(const float* __restrict__ b1, const float* __restrict__ b3) {
    int t = blockIdx.x, k = blockIdx.y;
    int row = t * TOPK + k;
    int e = g_idx[row];
    __shared__ float l1[RNK], l3[RNK];
    if (threadIdx.x < RNK) l1[threadIdx.x] = g_lr1[row * RNK + threadIdx.x];
    else if (threadIdx.x < 2 * RNK) l3[threadIdx.x - RNK] = g_lr3[row * RNK + threadIdx.x - RNK];
    __syncthreads();
    for (int f = threadIdx.x; f < FDIM; f += blockDim.x) {
        const float4* b1r = (const float4*)(b1 + ((size_t)e * FDIM + f) * RNK);
        const float4* b3r = (const float4*)(b3 + ((size_t)e * FDIM + f) * RNK);
        float h1 = g_base1[t * FDIM + f];
        float h3 = g_base3[t * FDIM + f];
#pragma unroll
        for (int q = 0; q < 4; q++) {
            float4 v1 = b1r[q], v3 = b3r[q];
            h1 += l1[q*4+0]*v1.x + l1[q*4+1]*v1.y + l1[q*4+2]*v1.z + l1[q*4+3]*v1.w;
            h3 += l3[q*4+0]*v3.x + l3[q*4+1]*v3.y + l3[q*4+2]*v3.z + l3[q*4+3]*v3.w;
        }
        float s = h1 / (1.f + expf(-h1));       // silu
        g_act[(size_t)row * FDIM + f] = s * h3;
    }
}

// ---------------- K6: LoRA-A down projection --------------------------------
__global__ void k_lora2(const float* __restrict__ a2) {
    int t = blockIdx.x, k = blockIdx.y;
    int row = t * TOPK + k;
    int e = g_idx[row];
    int w = threadIdx.x >> 5, l = threadIdx.x & 31;  // 16 warps = 16 ranks
    const float* ar = a2 + ((size_t)e * RNK + w) * FDIM;
    const float* actr = g_act + (size_t)row * FDIM;
    float s = 0.f;
    for (int f = l; f < FDIM; f += 32) s += actr[f] * ar[f];
    for (int o = 16; o; o >>= 1) s += __shfl_xor_sync(0xffffffffu, s, o);
    if (l == 0) g_lr2[row * RNK + w] = LSCALE * s;
}

// ---------------- K8: LoRA-B down + expert mix ------------------------------
__global__ void k_mix(const float* __restrict__ b2, float* __restrict__ out) {
    int t = blockIdx.x;
    __shared__ float l2[TOPK][RNK];
    __shared__ int   se[TOPK];
    __shared__ float sw[TOPK];
    if (threadIdx.x < TOPK * RNK) {
        int k = threadIdx.x / RNK, r = threadIdx.x % RNK;
        l2[k][r] = g_lr2[(t * TOPK + k) * RNK + r];
    }
    if (threadIdx.x < TOPK) {
        se[threadIdx.x] = g_idx[t * TOPK + threadIdx.x];
        sw[threadIdx.x] = g_wgt[t * TOPK + threadIdx.x];
    }
    __syncthreads();
    for (int d = threadIdx.x; d < DDIM; d += blockDim.x) {
        float o = 0.f;
#pragma unroll
        for (int k = 0; k < TOPK; k++) {
            int row = t * TOPK + k;
            float v = g_y[(size_t)row * DDIM + d];
            const float4* br = (const float4*)(b2 + ((size_t)se[k] * DDIM + d) * RNK);
#pragma unroll
            for (int q = 0; q < 4; q++) {
                float4 b = br[q];
                v += l2[k][q*4+0]*b.x + l2[k][q*4+1]*b.y + l2[k][q*4+2]*b.z + l2[k][q*4+3]*b.w;
            }
            o += sw[k] * v;
        }
        out[t * DDIM + d] = o;
    }
}

// ---------------- launch ----------------------------------------------------
extern "C" void kernel_launch(void* const* d_in, const int* in_sizes, int n_in,
                              void* d_out, int out_size) {
    const float* x      = (const float*)d_in[0];   // [1,512,1024]
    const float* norm_w = (const float*)d_in[1];   // [1024]
    const float* w1     = (const float*)d_in[2];   // [4096,1024]
    const float* w3     = (const float*)d_in[3];   // [4096,1024]
    const float* w2     = (const float*)d_in[4];   // [1024,4096]
    const float* gate_w = (const float*)d_in[5];   // [8,1024]
    const float* a1     = (const float*)d_in[6];   // [8,16,1024]
    const float* b1     = (const float*)d_in[7];   // [8,4096,16]
    const float* a3     = (const float*)d_in[8];
    const float* b3     = (const float*)d_in[9];
    const float* a2     = (const float*)d_in[10];  // [8,16,4096]
    const float* b2     = (const float*)d_in[11];  // [8,1024,16]
    float* out = (float*)d_out;

    float* t_ptr;    cudaGetSymbolAddress((void**)&t_ptr,    g_t);
    float* base1;    cudaGetSymbolAddress((void**)&base1,    g_base1);
    float* base3;    cudaGetSymbolAddress((void**)&base3,    g_base3);
    float* act_ptr;  cudaGetSymbolAddress((void**)&act_ptr,  g_act);
    float* y_ptr;    cudaGetSymbolAddress((void**)&y_ptr,    g_y);

    k_rmsnorm<<<T_TOK, 256>>>(x, norm_w);
    k_router<<<T_TOK, 256>>>(gate_w);
    k_lora_a<<<dim3(T_TOK, TOPK), 256>>>(a1, a3);

    // base up projections: [512,4096] = t @ w1^T / w3^T
    k_sgemm_nt<<<dim3(FDIM / BN, T_TOK / BM), 256>>>(T_TOK, FDIM, DDIM, t_ptr, w1, base1);
    k_sgemm_nt<<<dim3(FDIM / BN, T_TOK / BM), 256>>>(T_TOK, FDIM, DDIM, t_ptr, w3, base3);

    k_act<<<dim3(T_TOK, TOPK), 256>>>(b1, b3);
    k_lora2<<<dim3(T_TOK, TOPK), 512>>>(a2);

    // down projection: [1024,1024] = act @ w2^T
    k_sgemm_nt<<<dim3(DDIM / BN, (T_TOK * TOPK) / BM), 256>>>(T_TOK * TOPK, DDIM, FDIM,
                                                             act_ptr, w2, y_ptr);
    k_mix<<<T_TOK, 256>>>(b2, out);
}

// round 2
// speedup vs baseline: 1.5728x; 1.5728x over previous
#include <cuda_runtime.h>
#include <math.h>

#define T_TOK 512
#define DDIM  1024
#define FDIM  4096
#define NEXP  8
#define RNK   16
#define TOPK  2
#define LSCALE 2.0f
#define EPS   1e-6f

// ---------------- scratch (device globals; no allocation allowed) ----------
__device__ float g_t[T_TOK * DDIM];                 // normalized tokens
__device__ float g_base1[T_TOK * FDIM];             // t @ w1^T
__device__ float g_base3[T_TOK * FDIM];             // t @ w3^T
__device__ int   g_idx[T_TOK * TOPK];               // routed expert ids
__device__ float g_wgt[T_TOK * TOPK];               // renormalized weights
__device__ float g_lr1[T_TOK * TOPK * RNK];
__device__ float g_lr3[T_TOK * TOPK * RNK];
__device__ float g_act[T_TOK * TOPK * FDIM];        // silu(h1)*h3
__device__ float g_lr2[T_TOK * TOPK * RNK];
__device__ float g_y[T_TOK * TOPK * DDIM];          // act @ w2^T
__device__ int   g_cnt[NEXP];
__device__ int   g_lst[NEXP * T_TOK];               // per-expert row lists

// ---------------- fast all-FMA silu (no MUFU) -------------------------------
__device__ __forceinline__ float fast_silu(float x) {
    float u = -x * 1.442695041f;                 // -x * log2(e)
    float rn = u + 12582912.f;                   // magic round-to-int
    float n = rn - 12582912.f;
    float f = u - n;                             // frac in [-0.5, 0.5]
    float p = 1.3333558146e-3f;                  // 2^f Taylor (deg 5)
    p = fmaf(p, f, 9.6181291077e-3f);
    p = fmaf(p, f, 5.5504108664e-2f);
    p = fmaf(p, f, 2.4022650696e-1f);
    p = fmaf(p, f, 6.9314718056e-1f);
    p = fmaf(p, f, 1.0f);
    int ei = __float2int_rn(n);
    ei = ei > 60 ? 60 : (ei < -126 ? -126 : ei);
    float s = __int_as_float((ei + 127) << 23);
    float y = p * s;                             // e^{-x}
    float d = 1.0f + y;
    float r = __int_as_float(0x7EF311C4 - __float_as_int(d));  // ~1/d seed
    r = r * fmaf(-d, r, 2.0f);
    r = r * fmaf(-d, r, 2.0f);
    r = r * fmaf(-d, r, 2.0f);
    return x * r;
}

// ---------------- K1: RMSNorm ----------------------------------------------
__global__ void k_rmsnorm(const float* __restrict__ x, const float* __restrict__ nw) {
    int t = blockIdx.x;
    const float* xr = x + t * DDIM;
    float ss = 0.f;
    for (int i = threadIdx.x; i < DDIM; i += blockDim.x) {
        float v = xr[i];
        ss += v * v;
    }
    __shared__ float sred[32];
    for (int o = 16; o; o >>= 1) ss += __shfl_xor_sync(0xffffffffu, ss, o);
    if ((threadIdx.x & 31) == 0) sred[threadIdx.x >> 5] = ss;
    __syncthreads();
    if (threadIdx.x < 32) {
        float v = (threadIdx.x < (blockDim.x >> 5)) ? sred[threadIdx.x] : 0.f;
        for (int o = 16; o; o >>= 1) v += __shfl_xor_sync(0xffffffffu, v, o);
        if (threadIdx.x == 0) sred[0] = v;
    }
    __syncthreads();
    float scale = rsqrtf(sred[0] / (float)DDIM + EPS);
    for (int i = threadIdx.x; i < DDIM; i += blockDim.x)
        g_t[t * DDIM + i] = xr[i] * scale * nw[i];
}

// ---------------- K2: router (softmax -> top2 -> renorm) --------------------
__global__ void k_router(const float* __restrict__ gw) {
    int t = blockIdx.x;
    int w = threadIdx.x >> 5, l = threadIdx.x & 31;
    const float* tr = g_t + t * DDIM;
    const float* gr = gw + w * DDIM;
    float s = 0.f;
    for (int i = l; i < DDIM; i += 32) s += tr[i] * gr[i];
    for (int o = 16; o; o >>= 1) s += __shfl_xor_sync(0xffffffffu, s, o);
    __shared__ float logits[NEXP];
    if (l == 0) logits[w] = s;
    __syncthreads();
    if (threadIdx.x == 0) {
        float mx = logits[0];
        for (int e = 1; e < NEXP; e++) mx = fmaxf(mx, logits[e]);
        float p[NEXP], sum = 0.f;
        for (int e = 0; e < NEXP; e++) { p[e] = expf(logits[e] - mx); sum += p[e]; }
        for (int e = 0; e < NEXP; e++) p[e] /= sum;
        int i0 = 0;
        for (int e = 1; e < NEXP; e++) if (p[e] > p[i0]) i0 = e;
        int i1 = -1;
        for (int e = 0; e < NEXP; e++) {
            if (e == i0) continue;
            if (i1 < 0 || p[e] > p[i1]) i1 = e;
        }
        float w0 = p[i0], w1 = p[i1], tw = w0 + w1;
        g_idx[t * 2 + 0] = i0;  g_idx[t * 2 + 1] = i1;
        g_wgt[t * 2 + 0] = w0 / tw;  g_wgt[t * 2 + 1] = w1 / tw;
    }
}

// ---------------- K2b: build per-expert row lists ---------------------------
__global__ void k_build() {
    int tid = threadIdx.x;
    if (tid < NEXP) g_cnt[tid] = 0;
    __syncthreads();
    int e = g_idx[tid];
    int pos = atomicAdd(&g_cnt[e], 1);
    g_lst[e * T_TOK + pos] = tid;
}

// ---------------- K3: LoRA-A up projections ---------------------------------
__global__ void k_lora_a(const float* __restrict__ a1, const float* __restrict__ a3) {
    int t = blockIdx.x, k = blockIdx.y;
    int row = t * TOPK + k;
    int e = g_idx[row];
    const float* tr = g_t + t * DDIM;
    int w = threadIdx.x >> 5, l = threadIdx.x & 31;
    for (int task = w; task < 2 * RNK; task += 8) {
        int mat = task >> 4, r = task & 15;
        const float* ar = (mat ? a3 : a1) + ((size_t)e * RNK + r) * DDIM;
        float s = 0.f;
        for (int i = l; i < DDIM; i += 32) s += tr[i] * ar[i];
        for (int o = 16; o; o >>= 1) s += __shfl_xor_sync(0xffffffffu, s, o);
        if (l == 0) {
            float* dst = mat ? g_lr3 : g_lr1;
            dst[row * RNK + r] = LSCALE * s;
        }
    }
}

// ---------------- tf32 tensor-core NT GEMM ----------------------------------
// C[M,N] = A[M,K] @ B[N,K]^T.  BM=64, BN=128, BK=16, 256 thr (8 warps, 2x4),
// warp tile 32x32 (2 m-tiles x 4 n-tiles of m16n8k8). Register-staged double
// buffer; fp32->tf32 rna conversion at STS time. Pad stride 20 (conflict-free).
#define GBM 64
#define GBN 128
#define GBK 16
#define GST 20

__device__ __forceinline__ unsigned f2tf(float x) {
    unsigned u;
    asm("cvt.rna.tf32.f32 %0, %1;" : "=r"(u) : "f"(x));
    return u;
}

__device__ __forceinline__ void mma_tf32(float* c, const unsigned* a, const unsigned* b) {
    asm volatile(
        "mma.sync.aligned.m16n8k8.row.col.f32.tf32.tf32.f32 "
        "{%0,%1,%2,%3}, {%4,%5,%6,%7}, {%8,%9}, {%0,%1,%2,%3};"
        : "+f"(c[0]), "+f"(c[1]), "+f"(c[2]), "+f"(c[3])
        : "r"(a[0]), "r"(a[1]), "r"(a[2]), "r"(a[3]), "r"(b[0]), "r"(b[1]));
}

__global__ void __launch_bounds__(256)
k_mma_nt(int M, int N, int K,
         const float* __restrict__ A, const float* __restrict__ B,
         float* __restrict__ C) {
    __shared__ unsigned As[2][GBM * GST];
    __shared__ unsigned Bs[2][GBN * GST];
    int bm = blockIdx.y * GBM, bn = blockIdx.x * GBN;
    int tid = threadIdx.x;
    int lane = tid & 31, wid = tid >> 5;
    int wm = wid & 1, wn = wid >> 1;
    int qr = lane >> 2, qc = lane & 3;

    int arow = tid >> 2;              // 0..63
    int ac4  = (tid & 3) * 4;         // 0,4,8,12
    const float* Ag  = A + (size_t)(bm + arow) * K + ac4;
    const float* Bg0 = B + (size_t)(bn + arow) * K + ac4;
    const float* Bg1 = B + (size_t)(bn + arow + 64) * K + ac4;

    float4 ra  = *(const float4*)(Ag);
    float4 rb0 = *(const float4*)(Bg0);
    float4 rb1 = *(const float4*)(Bg1);

    float acc[2][4][4];
#pragma unroll
    for (int i = 0; i < 2; i++)
#pragma unroll
        for (int j = 0; j < 4; j++)
#pragma unroll
            for (int q = 0; q < 4; q++) acc[i][j][q] = 0.f;

    int niter = K / GBK;
    for (int it = 0; it < niter; ++it) {
        int s = it & 1;
        unsigned* pa = &As[s][arow * GST + ac4];
        pa[0] = f2tf(ra.x); pa[1] = f2tf(ra.y); pa[2] = f2tf(ra.z); pa[3] = f2tf(ra.w);
        unsigned* pb0 = &Bs[s][arow * GST + ac4];
        pb0[0] = f2tf(rb0.x); pb0[1] = f2tf(rb0.y); pb0[2] = f2tf(rb0.z); pb0[3] = f2tf(rb0.w);
        unsigned* pb1 = &Bs[s][(arow + 64) * GST + ac4];
        pb1[0] = f2tf(rb1.x); pb1[1] = f2tf(rb1.y); pb1[2] = f2tf(rb1.z); pb1[3] = f2tf(rb1.w);
        __syncthreads();
        if (it + 1 < niter) {
            int k0 = (it + 1) * GBK;
            ra  = *(const float4*)(Ag + k0);
            rb0 = *(const float4*)(Bg0 + k0);
            rb1 = *(const float4*)(Bg1 + k0);
        }
#pragma unroll
        for (int ks = 0; ks < 2; ks++) {
            int kk = ks * 8;
            unsigned af[2][4], bf[4][2];
#pragma unroll
            for (int mt = 0; mt < 2; mt++) {
                const unsigned* base = &As[s][(wm * 32 + mt * 16 + qr) * GST + kk + qc];
                af[mt][0] = base[0];
                af[mt][1] = base[8 * GST];
                af[mt][2] = base[4];
                af[mt][3] = base[8 * GST + 4];
            }
#pragma unroll
            for (int nt = 0; nt < 4; nt++) {
                const unsigned* base = &Bs[s][(wn * 32 + nt * 8 + qr) * GST + kk + qc];
                bf[nt][0] = base[0];
                bf[nt][1] = base[4];
            }
#pragma unroll
            for (int mt = 0; mt < 2; mt++)
#pragma unroll
                for (int nt = 0; nt < 4; nt++)
                    mma_tf32(acc[mt][nt], af[mt], bf[nt]);
        }
        __syncthreads();
    }
#pragma unroll
    for (int mt = 0; mt < 2; mt++)
#pragma unroll
        for (int nt = 0; nt < 4; nt++) {
            int row0 = bm + wm * 32 + mt * 16 + qr;
            int col  = bn + wn * 32 + nt * 8 + 2 * qc;
            float2 v0 = make_float2(acc[mt][nt][0], acc[mt][nt][1]);
            float2 v1 = make_float2(acc[mt][nt][2], acc[mt][nt][3]);
            *(float2*)&C[(size_t)row0 * N + col] = v0;
            *(float2*)&C[(size_t)(row0 + 8) * N + col] = v1;
        }
}

// ---------------- K5: expert-grouped LoRA-B + SwiGLU ------------------------
// grid (E, F/512), 512 threads, 1 f per thread; b1/b3 rows in registers.
__global__ void __launch_bounds__(512)
k_act2(const float* __restrict__ b1, const float* __restrict__ b3) {
    int e = blockIdx.x;
    int f = blockIdx.y * 512 + threadIdx.x;
    float br1[RNK], br3[RNK];
    const float4* p1 = (const float4*)(b1 + ((size_t)e * FDIM + f) * RNK);
    const float4* p3 = (const float4*)(b3 + ((size_t)e * FDIM + f) * RNK);
#pragma unroll
    for (int q = 0; q < 4; q++) {
        float4 v = p1[q];
        br1[q*4+0] = v.x; br1[q*4+1] = v.y; br1[q*4+2] = v.z; br1[q*4+3] = v.w;
        v = p3[q];
        br3[q*4+0] = v.x; br3[q*4+1] = v.y; br3[q*4+2] = v.z; br3[q*4+3] = v.w;
    }
    int n = g_cnt[e];
    __shared__ float s1[16][RNK], s3[16][RNK];
    __shared__ int sr[16];
    for (int i0 = 0; i0 < n; i0 += 16) {
        int batch = min(16, n - i0);
        __syncthreads();
        int q = threadIdx.x;
        int j = q >> 5, v = q & 31;
        if (j < batch) {
            int row = g_lst[e * T_TOK + i0 + j];
            if (v == 0) sr[j] = row;
            if (v < RNK) s1[j][v] = g_lr1[row * RNK + v];
            else         s3[j][v - RNK] = g_lr3[row * RNK + v - RNK];
        }
        __syncthreads();
        for (int jj = 0; jj < batch; jj++) {
            int row = sr[jj];
            int t = row >> 1;
            float h1 = __ldg(&g_base1[(size_t)t * FDIM + f]);
            float h3 = __ldg(&g_base3[(size_t)t * FDIM + f]);
#pragma unroll
            for (int r = 0; r < RNK; r++) {
                h1 = fmaf(s1[jj][r], br1[r], h1);
                h3 = fmaf(s3[jj][r], br3[r], h3);
            }
            g_act[(size_t)row * FDIM + f] = fast_silu(h1) * h3;
        }
    }
}

// ---------------- K6: expert-grouped LoRA-A down projection -----------------
// grid (E, 16): blocks of up to 32 rows; F chunked by 512 through smem.
#define L2FC 512
#define L2ST 516
__global__ void __launch_bounds__(256)
k_lora2g(const float* __restrict__ a2) {
    extern __shared__ float sm[];
    float* s_act = sm;                 // [32][516]
    float* s_a2  = sm + 32 * L2ST;     // [16][516]
    int e = blockIdx.x, rb = blockIdx.y;
    int n = g_cnt[e];
    int r0 = rb * 32;
    if (r0 >= n) return;
    int nrows = min(32, n - r0);
    int tid = threadIdx.x;
    __shared__ int s_row[32];
    if (tid < 32) s_row[tid] = (tid < nrows) ? g_lst[e * T_TOK + r0 + tid] : -1;
    __syncthreads();
    int myrow = tid >> 3;
    int rp = (tid & 7) * 2;
    float acc0 = 0.f, acc1 = 0.f;
    for (int f0 = 0; f0 < FDIM; f0 += L2FC) {
        for (int q = tid; q < 32 * 128; q += 256) {
            int j = q >> 7, c4 = q & 127;
            float4 v = make_float4(0.f, 0.f, 0.f, 0.f);
            int row = s_row[j];
            if (row >= 0) v = *(const float4*)(g_act + (size_t)row * FDIM + f0 + c4 * 4);
            float* d = s_act + j * L2ST + c4 * 4;
            d[0] = v.x; d[1] = v.y; d[2] = v.z; d[3] = v.w;
        }
        for (int q = tid; q < 16 * 128; q += 256) {
            int j = q >> 7, c4 = q & 127;
            float4 v = *(const float4*)(a2 + ((size_t)e * RNK + j) * FDIM + f0 + c4 * 4);
            float* d = s_a2 + j * L2ST + c4 * 4;
            d[0] = v.x; d[1] = v.y; d[2] = v.z; d[3] = v.w;
        }
        __syncthreads();
        const float* ar0 = s_a2 + rp * L2ST;
        const float* ar1 = s_a2 + (rp + 1) * L2ST;
        const float* ac = s_act + myrow * L2ST;
#pragma unroll 8
        for (int f = 0; f < L2FC; f++) {
            float a = ac[f];
            acc0 = fmaf(a, ar0[f], acc0);
            acc1 = fmaf(a, ar1[f], acc1);
        }
        __syncthreads();
    }
    if (myrow < nrows) {
        int row = s_row[myrow];
        g_lr2[row * RNK + rp]     = LSCALE * acc0;
        g_lr2[row * RNK + rp + 1] = LSCALE * acc1;
    }
}

// ---------------- K8: LoRA-B down + expert mix ------------------------------
__global__ void k_mix(const float* __restrict__ b2, float* __restrict__ out) {
    int t = blockIdx.x;
    __shared__ float l2[TOPK][RNK];
    __shared__ int   se[TOPK];
    __shared__ float sw[TOPK];
    if (threadIdx.x < TOPK * RNK) {
        int k = threadIdx.x / RNK, r = threadIdx.x % RNK;
        l2[k][r] = g_lr2[(t * TOPK + k) * RNK + r];
    }
    if (threadIdx.x < TOPK) {
        se[threadIdx.x] = g_idx[t * TOPK + threadIdx.x];
        sw[threadIdx.x] = g_wgt[t * TOPK + threadIdx.x];
    }
    __syncthreads();
    for (int d = threadIdx.x; d < DDIM; d += blockDim.x) {
        float o = 0.f;
#pragma unroll
        for (int k = 0; k < TOPK; k++) {
            int row = t * TOPK + k;
            float v = g_y[(size_t)row * DDIM + d];
            const float4* br = (const float4*)(b2 + ((size_t)se[k] * DDIM + d) * RNK);
#pragma unroll
            for (int q = 0; q < 4; q++) {
                float4 b = br[q];
                v += l2[k][q*4+0]*b.x + l2[k][q*4+1]*b.y + l2[k][q*4+2]*b.z + l2[k][q*4+3]*b.w;
            }
            o += sw[k] * v;
        }
        out[t * DDIM + d] = o;
    }
}

// ---------------- launch ----------------------------------------------------
extern "C" void kernel_launch(void* const* d_in, const int* in_sizes, int n_in,
                              void* d_out, int out_size) {
    const float* x      = (const float*)d_in[0];
    const float* norm_w = (const float*)d_in[1];
    const float* w1     = (const float*)d_in[2];
    const float* w3     = (const float*)d_in[3];
    const float* w2     = (const float*)d_in[4];
    const float* gate_w = (const float*)d_in[5];
    const float* a1     = (const float*)d_in[6];
    const float* b1     = (const float*)d_in[7];
    const float* a3     = (const float*)d_in[8];
    const float* b3     = (const float*)d_in[9];
    const float* a2     = (const float*)d_in[10];
    const float* b2     = (const float*)d_in[11];
    float* out = (float*)d_out;

    float* t_ptr;   cudaGetSymbolAddress((void**)&t_ptr,   g_t);
    float* base1;   cudaGetSymbolAddress((void**)&base1,   g_base1);
    float* base3;   cudaGetSymbolAddress((void**)&base3,   g_base3);
    float* act_ptr; cudaGetSymbolAddress((void**)&act_ptr, g_act);
    float* y_ptr;   cudaGetSymbolAddress((void**)&y_ptr,   g_y);

    static int smem_set = 0;
    if (!smem_set) {
        cudaFuncSetAttribute(k_lora2g, cudaFuncAttributeMaxDynamicSharedMemorySize,
                             48 * L2ST * 4);
        smem_set = 1;
    }

    k_rmsnorm<<<T_TOK, 256>>>(x, norm_w);
    k_router<<<T_TOK, 256>>>(gate_w);
    k_build<<<1, T_TOK * TOPK>>>();
    k_lora_a<<<dim3(T_TOK, TOPK), 256>>>(a1, a3);

    k_mma_nt<<<dim3(FDIM / GBN, T_TOK / GBM), 256>>>(T_TOK, FDIM, DDIM, t_ptr, w1, base1);
    k_mma_nt<<<dim3(FDIM / GBN, T_TOK / GBM), 256>>>(T_TOK, FDIM, DDIM, t_ptr, w3, base3);

    k_act2<<<dim3(NEXP, FDIM / 512), 512>>>(b1, b3);
    k_lora2g<<<dim3(NEXP, 16), 256, 48 * L2ST * 4>>>(a2);

    k_mma_nt<<<dim3(DDIM / GBN, (T_TOK * TOPK) / GBM), 256>>>(T_TOK * TOPK, DDIM, FDIM,
                                                              act_ptr, w2, y_ptr);
    k_mix<<<T_TOK, 256>>>(b2, out);
}